// round 11
// baseline (speedup 1.0000x reference)
#include <cuda_runtime.h>

#define NB 8192
#define ND 256
#define BM 128
#define BN 64
#define KC 32
#define SPAD 34          // KC + 2 pad: 136B row stride, 8B aligned, bank-stride 2 per col
#define INV_T 14.2857142857142857f

// ---- scratch (no allocs allowed; __device__ globals are the sanctioned path) ----
__device__ float g_norm[NB * ND];     // L2-normalized embeddings (8 MB, fits in L2)
__device__ int   g_lab[NB];
__device__ float g_sum_all[NB];       // sum_{j!=i} exp(sim_ij)
__device__ float g_sum_pos[NB];       // sum_{j!=i, lab_j==lab_i} exp(sim_ij)

// ---------------------------------------------------------------------------
// Kernel 0: label dtype detect + convert to int32, zero accumulators.
// Must re-zero every launch (graph replays rerun the whole sequence).
// ---------------------------------------------------------------------------
__global__ void prep_kernel(const void* __restrict__ labels_raw) {
    __shared__ int is64;
    const int tid = threadIdx.x;
    if (tid == 0) {
        // int64 labels in [0,1000) => every odd 32-bit word of the first 32
        // labels is 0. For int32 labels, P(all 32 odd words zero) ~ 1e-96.
        const int* w = (const int*)labels_raw;
        int z = 1;
        #pragma unroll
        for (int i = 1; i < 64; i += 2) z &= (w[i] == 0);
        is64 = z;
    }
    __syncthreads();
    if (is64) {
        const long long* l = (const long long*)labels_raw;
        for (int i = tid; i < NB; i += blockDim.x) {
            g_lab[i] = (int)l[i];
            g_sum_all[i] = 0.0f;
            g_sum_pos[i] = 0.0f;
        }
    } else {
        const int* l = (const int*)labels_raw;
        for (int i = tid; i < NB; i += blockDim.x) {
            g_lab[i] = l[i];
            g_sum_all[i] = 0.0f;
            g_sum_pos[i] = 0.0f;
        }
    }
}

// ---------------------------------------------------------------------------
// Kernel 1: row L2-normalize. One warp per row, 2x float4 per lane.
// ---------------------------------------------------------------------------
__global__ void normalize_kernel(const float* __restrict__ x) {
    const int row  = (blockIdx.x * blockDim.x + threadIdx.x) >> 5;
    const int lane = threadIdx.x & 31;
    if (row >= NB) return;

    const float4* xr = (const float4*)(x + (size_t)row * ND);
    float4 v0 = xr[lane];
    float4 v1 = xr[lane + 32];
    float ss = v0.x*v0.x + v0.y*v0.y + v0.z*v0.z + v0.w*v0.w
             + v1.x*v1.x + v1.y*v1.y + v1.z*v1.z + v1.w*v1.w;
    #pragma unroll
    for (int o = 16; o; o >>= 1) ss += __shfl_xor_sync(0xffffffffu, ss, o);

    const float inv = 1.0f / fmaxf(sqrtf(ss), 1e-12f);
    v0.x *= inv; v0.y *= inv; v0.z *= inv; v0.w *= inv;
    v1.x *= inv; v1.y *= inv; v1.z *= inv; v1.w *= inv;

    float4* o4 = (float4*)(g_norm + (size_t)row * ND);
    o4[lane]      = v0;
    o4[lane + 32] = v1;
}

// ---------------------------------------------------------------------------
// Kernel 2: fused sim-tile GEMM + exp + masked row-sum accumulation.
// BM=128 rows x BN=64 cols per block, 256 threads, 8x4 micro-tile,
// K packed pairwise into fma.rn.f32x2 (full-rate fp32 on sm_103a).
// ---------------------------------------------------------------------------
__global__ __launch_bounds__(256, 2) void sim_kernel() {
    __shared__ float As[BM][SPAD];
    __shared__ float Bs[BN][SPAD];

    const int tid = threadIdx.x;
    const int tx  = tid & 15;    // column group (16)
    const int ty  = tid >> 4;    // row group (16)
    const int rowBase = blockIdx.y * BM;
    const int colBase = blockIdx.x * BN;

    unsigned long long acc[8][4];
    #pragma unroll
    for (int r = 0; r < 8; r++)
        #pragma unroll
        for (int c = 0; c < 4; c++) acc[r][c] = 0ull;  // (0.0f, 0.0f)

    for (int kc = 0; kc < ND / KC; ++kc) {
        const int kOff = kc * KC;
        // A chunk: 128 x 32 floats = 1024 float4, 4 per thread (coalesced 128B rows)
        #pragma unroll
        for (int i = 0; i < 4; i++) {
            const int idx = tid + i * 256;
            const int r = idx >> 3, k4 = idx & 7;
            float4 v = *(const float4*)&g_norm[(size_t)(rowBase + r) * ND + kOff + k4 * 4];
            float2* dst = (float2*)&As[r][k4 * 4];
            dst[0] = make_float2(v.x, v.y);
            dst[1] = make_float2(v.z, v.w);
        }
        // B chunk: 64 x 32 floats = 512 float4, 2 per thread
        #pragma unroll
        for (int i = 0; i < 2; i++) {
            const int idx = tid + i * 256;
            const int r = idx >> 3, k4 = idx & 7;
            float4 v = *(const float4*)&g_norm[(size_t)(colBase + r) * ND + kOff + k4 * 4];
            float2* dst = (float2*)&Bs[r][k4 * 4];
            dst[0] = make_float2(v.x, v.y);
            dst[1] = make_float2(v.z, v.w);
        }
        __syncthreads();

        #pragma unroll 4
        for (int k2 = 0; k2 < KC / 2; k2++) {
            unsigned long long a2[8], b2[4];
            #pragma unroll
            for (int rr = 0; rr < 8; rr++)
                a2[rr] = *(const unsigned long long*)&As[ty + rr * 16][k2 * 2];
            #pragma unroll
            for (int cc = 0; cc < 4; cc++)
                b2[cc] = *(const unsigned long long*)&Bs[tx + cc * 16][k2 * 2];
            #pragma unroll
            for (int rr = 0; rr < 8; rr++)
                #pragma unroll
                for (int cc = 0; cc < 4; cc++)
                    asm("fma.rn.f32x2 %0, %1, %2, %0;"
                        : "+l"(acc[rr][cc]) : "l"(a2[rr]), "l"(b2[cc]));
        }
        __syncthreads();
    }

    // ---- epilogue: exp + masked per-row partial sums ----
    int gi[8], li[8], gj[4], lj[4];
    #pragma unroll
    for (int rr = 0; rr < 8; rr++) { gi[rr] = rowBase + ty + rr * 16; li[rr] = g_lab[gi[rr]]; }
    #pragma unroll
    for (int cc = 0; cc < 4; cc++) { gj[cc] = colBase + tx + cc * 16; lj[cc] = g_lab[gj[cc]]; }

    float pall[8], ppos[8];
    #pragma unroll
    for (int rr = 0; rr < 8; rr++) { pall[rr] = 0.0f; ppos[rr] = 0.0f; }

    #pragma unroll
    for (int rr = 0; rr < 8; rr++) {
        #pragma unroll
        for (int cc = 0; cc < 4; cc++) {
            const unsigned long long v = acc[rr][cc];
            const float lo = __uint_as_float((unsigned)(v & 0xffffffffu));
            const float hi = __uint_as_float((unsigned)(v >> 32));
            const float s = (lo + hi) * INV_T;          // |s| <= 14.29, exp safe
            if (gi[rr] != gj[cc]) {
                const float e = __expf(s);
                pall[rr] += e;
                ppos[rr] += (li[rr] == lj[cc]) ? e : 0.0f;
            }
        }
    }

    // reduce across the 16 tx lanes (lane = (ty&1)*16 + tx, xor<=8 stays in-group)
    #pragma unroll
    for (int o = 8; o; o >>= 1) {
        #pragma unroll
        for (int rr = 0; rr < 8; rr++) {
            pall[rr] += __shfl_xor_sync(0xffffffffu, pall[rr], o);
            ppos[rr] += __shfl_xor_sync(0xffffffffu, ppos[rr], o);
        }
    }
    if (tx == 0) {
        #pragma unroll
        for (int rr = 0; rr < 8; rr++) {
            atomicAdd(&g_sum_all[gi[rr]], pall[rr]);
            atomicAdd(&g_sum_pos[gi[rr]], ppos[rr]);
        }
    }
}

// ---------------------------------------------------------------------------
// Kernel 3: final scalar reduce. loss_i = log(S_all) - log(S_pos), mean over
// rows with positives (S_pos > 0 iff any positive exists: exp >= 6e-7 > 0).
// ---------------------------------------------------------------------------
__global__ void reduce_kernel(float* __restrict__ out) {
    __shared__ float sl[256];
    __shared__ int   sc[256];
    const int tid = threadIdx.x;
    float loss = 0.0f;
    int cnt = 0;
    for (int i = tid; i < NB; i += 256) {
        const float sp = g_sum_pos[i];
        if (sp > 0.0f) {
            loss += logf(g_sum_all[i]) - logf(sp);
            cnt++;
        }
    }
    sl[tid] = loss; sc[tid] = cnt;
    __syncthreads();
    #pragma unroll
    for (int o = 128; o; o >>= 1) {
        if (tid < o) { sl[tid] += sl[tid + o]; sc[tid] += sc[tid + o]; }
        __syncthreads();
    }
    if (tid == 0) out[0] = (sc[0] > 0) ? (sl[0] / (float)sc[0]) : 0.0f;
}

// ---------------------------------------------------------------------------
extern "C" void kernel_launch(void* const* d_in, const int* in_sizes, int n_in,
                              void* d_out, int out_size) {
    const float* emb    = (const float*)d_in[0];
    const void*  labels = d_in[1];

    prep_kernel<<<1, 256>>>(labels);
    normalize_kernel<<<NB * 32 / 256, 256>>>(emb);

    dim3 grid(NB / BN, NB / BM);   // (128, 64) = 8192 tiles
    sim_kernel<<<grid, 256>>>();

    reduce_kernel<<<1, 256>>>((float*)d_out);
}

// round 12
// speedup vs baseline: 1.9007x; 1.9007x over previous
#include <cuda_runtime.h>

#define NB 8192
#define ND 256
#define BM 128
#define BN 64
#define KC 32
#define SPAD 34          // KC + 2 pad: 136B row stride, 8B aligned, bank-stride 2 per col
#define INV_T 14.2857142857142857f
#define NTILES 4160      // sum_{bi=0}^{63} (128 - 2*bi) = 64*65

// ---- scratch (no allocs allowed; __device__ globals are the sanctioned path) ----
__device__ float g_norm[NB * ND];     // L2-normalized embeddings (8 MB, fits in L2)
__device__ int   g_lab[NB];
__device__ float g_sum_all[NB];       // sum_{j!=i} exp(sim_ij)
__device__ float g_sum_pos[NB];       // sum_{j!=i, lab_j==lab_i} exp(sim_ij)

// ---------------------------------------------------------------------------
// Kernel 0: label dtype detect + convert to int32, zero accumulators.
// ---------------------------------------------------------------------------
__global__ void prep_kernel(const void* __restrict__ labels_raw) {
    __shared__ int is64;
    const int tid = threadIdx.x;
    if (tid == 0) {
        // int64 labels in [0,1000) => every odd 32-bit word of first 32 labels is 0.
        const int* w = (const int*)labels_raw;
        int z = 1;
        #pragma unroll
        for (int i = 1; i < 64; i += 2) z &= (w[i] == 0);
        is64 = z;
    }
    __syncthreads();
    if (is64) {
        const long long* l = (const long long*)labels_raw;
        for (int i = tid; i < NB; i += blockDim.x) {
            g_lab[i] = (int)l[i];
            g_sum_all[i] = 0.0f;
            g_sum_pos[i] = 0.0f;
        }
    } else {
        const int* l = (const int*)labels_raw;
        for (int i = tid; i < NB; i += blockDim.x) {
            g_lab[i] = l[i];
            g_sum_all[i] = 0.0f;
            g_sum_pos[i] = 0.0f;
        }
    }
}

// ---------------------------------------------------------------------------
// Kernel 1: row L2-normalize. One warp per row, 2x float4 per lane.
// ---------------------------------------------------------------------------
__global__ void normalize_kernel(const float* __restrict__ x) {
    const int row  = (blockIdx.x * blockDim.x + threadIdx.x) >> 5;
    const int lane = threadIdx.x & 31;
    if (row >= NB) return;

    const float4* xr = (const float4*)(x + (size_t)row * ND);
    float4 v0 = xr[lane];
    float4 v1 = xr[lane + 32];
    float ss = v0.x*v0.x + v0.y*v0.y + v0.z*v0.z + v0.w*v0.w
             + v1.x*v1.x + v1.y*v1.y + v1.z*v1.z + v1.w*v1.w;
    #pragma unroll
    for (int o = 16; o; o >>= 1) ss += __shfl_xor_sync(0xffffffffu, ss, o);

    const float inv = 1.0f / fmaxf(sqrtf(ss), 1e-12f);
    v0.x *= inv; v0.y *= inv; v0.z *= inv; v0.w *= inv;
    v1.x *= inv; v1.y *= inv; v1.z *= inv; v1.w *= inv;

    float4* o4 = (float4*)(g_norm + (size_t)row * ND);
    o4[lane]      = v0;
    o4[lane + 32] = v1;
}

// ---------------------------------------------------------------------------
// Kernel 2: SYMMETRIC fused sim-tile GEMM + exp + masked row/col accumulation.
// Only upper-triangular tiles (colBase >= rowBase) are enumerated; each tile
// contributes exp partials to BOTH its 128 row sums and (by symmetry) its
// 64 column sums. Tiles straddling the diagonal mask strictly to c > r, so
// every unordered pair is counted exactly once and the diagonal never.
// ---------------------------------------------------------------------------
__global__ __launch_bounds__(256, 2) void sim_kernel() {
    __shared__ float As[BM][SPAD];
    __shared__ float Bs[BN][SPAD];

    // ---- map linear tile id -> (bi, bj) with bj in [2*bi, 128) ----
    // cum(bi) = bi*(129 - bi); boundaries are exact in fp32 (perfect squares).
    const int t = blockIdx.x;
    int bi = (int)((129.0f - sqrtf((float)(16641 - 4 * t))) * 0.5f);
    while (bi * (129 - bi) > t) bi--;
    while ((bi + 1) * (129 - (bi + 1)) <= t) bi++;
    const int bj = 2 * bi + (t - bi * (129 - bi));

    const int rowBase = bi * BM;
    const int colBase = bj * BN;
    const bool strict = (colBase < rowBase + BM);   // diagonal-straddling tile

    const int tid = threadIdx.x;
    const int tx  = tid & 15;    // column group (16)
    const int ty  = tid >> 4;    // row group (16)

    unsigned long long acc[8][4];
    #pragma unroll
    for (int r = 0; r < 8; r++)
        #pragma unroll
        for (int c = 0; c < 4; c++) acc[r][c] = 0ull;  // (0.0f, 0.0f)

    for (int kc = 0; kc < ND / KC; ++kc) {
        const int kOff = kc * KC;
        #pragma unroll
        for (int i = 0; i < 4; i++) {
            const int idx = tid + i * 256;
            const int r = idx >> 3, k4 = idx & 7;
            float4 v = *(const float4*)&g_norm[(size_t)(rowBase + r) * ND + kOff + k4 * 4];
            float2* dst = (float2*)&As[r][k4 * 4];
            dst[0] = make_float2(v.x, v.y);
            dst[1] = make_float2(v.z, v.w);
        }
        #pragma unroll
        for (int i = 0; i < 2; i++) {
            const int idx = tid + i * 256;
            const int r = idx >> 3, k4 = idx & 7;
            float4 v = *(const float4*)&g_norm[(size_t)(colBase + r) * ND + kOff + k4 * 4];
            float2* dst = (float2*)&Bs[r][k4 * 4];
            dst[0] = make_float2(v.x, v.y);
            dst[1] = make_float2(v.z, v.w);
        }
        __syncthreads();

        #pragma unroll 4
        for (int k2 = 0; k2 < KC / 2; k2++) {
            unsigned long long a2[8], b2[4];
            #pragma unroll
            for (int rr = 0; rr < 8; rr++)
                a2[rr] = *(const unsigned long long*)&As[ty + rr * 16][k2 * 2];
            #pragma unroll
            for (int cc = 0; cc < 4; cc++)
                b2[cc] = *(const unsigned long long*)&Bs[tx + cc * 16][k2 * 2];
            #pragma unroll
            for (int rr = 0; rr < 8; rr++)
                #pragma unroll
                for (int cc = 0; cc < 4; cc++)
                    asm("fma.rn.f32x2 %0, %1, %2, %0;"
                        : "+l"(acc[rr][cc]) : "l"(a2[rr]), "l"(b2[cc]));
        }
        __syncthreads();
    }

    // ---- epilogue: exp + masked partial sums, BOTH directions ----
    int gi[8], li[8], gj[4], lj[4];
    #pragma unroll
    for (int rr = 0; rr < 8; rr++) { gi[rr] = rowBase + ty + rr * 16; li[rr] = g_lab[gi[rr]]; }
    #pragma unroll
    for (int cc = 0; cc < 4; cc++) { gj[cc] = colBase + tx + cc * 16; lj[cc] = g_lab[gj[cc]]; }

    float pall[8], ppos[8];   // row-direction partials
    float qall[4], qpos[4];   // column-direction partials (transpose contribution)
    #pragma unroll
    for (int rr = 0; rr < 8; rr++) { pall[rr] = 0.0f; ppos[rr] = 0.0f; }
    #pragma unroll
    for (int cc = 0; cc < 4; cc++) { qall[cc] = 0.0f; qpos[cc] = 0.0f; }

    #pragma unroll
    for (int rr = 0; rr < 8; rr++) {
        #pragma unroll
        for (int cc = 0; cc < 4; cc++) {
            if (!strict || gj[cc] > gi[rr]) {
                const unsigned long long v = acc[rr][cc];
                const float lo = __uint_as_float((unsigned)(v & 0xffffffffu));
                const float hi = __uint_as_float((unsigned)(v >> 32));
                const float e = __expf((lo + hi) * INV_T);   // |s| <= 14.29
                pall[rr] += e;
                qall[cc] += e;
                if (li[rr] == lj[cc]) { ppos[rr] += e; qpos[cc] += e; }
            }
        }
    }

    // ---- row reduction: across the 16 tx lanes (xor<=8 stays in 16-group) ----
    #pragma unroll
    for (int o = 8; o; o >>= 1) {
        #pragma unroll
        for (int rr = 0; rr < 8; rr++) {
            pall[rr] += __shfl_xor_sync(0xffffffffu, pall[rr], o);
            ppos[rr] += __shfl_xor_sync(0xffffffffu, ppos[rr], o);
        }
    }
    if (tx == 0) {
        #pragma unroll
        for (int rr = 0; rr < 8; rr++) {
            atomicAdd(&g_sum_all[gi[rr]], pall[rr]);
            atomicAdd(&g_sum_pos[gi[rr]], ppos[rr]);
        }
    }

    // ---- column reduction: combine ty-pair in-warp, stage per-warp in smem ----
    // lane = (ty&1)*16 + tx; xor 16 merges the two ty values in each warp.
    #pragma unroll
    for (int cc = 0; cc < 4; cc++) {
        qall[cc] += __shfl_xor_sync(0xffffffffu, qall[cc], 16);
        qpos[cc] += __shfl_xor_sync(0xffffffffu, qpos[cc], 16);
    }
    // Reuse As (dead after mainloop) as scratch: 8 warps x 64 cols x 2 arrays.
    float* sAll = &As[0][0];        // [8][64]
    float* sPos = sAll + 512;       // [8][64]
    const int w = tid >> 5;
    if ((tid & 31) < 16) {
        #pragma unroll
        for (int cc = 0; cc < 4; cc++) {
            sAll[w * 64 + cc * 16 + tx] = qall[cc];
            sPos[w * 64 + cc * 16 + tx] = qpos[cc];
        }
    }
    __syncthreads();
    if (tid < 64) {
        float a = 0.0f, p = 0.0f;
        #pragma unroll
        for (int ww = 0; ww < 8; ww++) {
            a += sAll[ww * 64 + tid];
            p += sPos[ww * 64 + tid];
        }
        atomicAdd(&g_sum_all[colBase + tid], a);
        atomicAdd(&g_sum_pos[colBase + tid], p);
    }
}

// ---------------------------------------------------------------------------
// Kernel 3: final scalar reduce. 1024 threads, unrolled for MLP.
// ---------------------------------------------------------------------------
__global__ void reduce_kernel(float* __restrict__ out) {
    __shared__ float sl[1024];
    __shared__ int   sc[1024];
    const int tid = threadIdx.x;
    float loss = 0.0f;
    int cnt = 0;
    float sp[8], sa[8];
    #pragma unroll
    for (int k = 0; k < 8; k++) {
        sp[k] = g_sum_pos[tid + k * 1024];
        sa[k] = g_sum_all[tid + k * 1024];
    }
    #pragma unroll
    for (int k = 0; k < 8; k++) {
        if (sp[k] > 0.0f) {
            loss += logf(sa[k]) - logf(sp[k]);
            cnt++;
        }
    }
    sl[tid] = loss; sc[tid] = cnt;
    __syncthreads();
    #pragma unroll
    for (int o = 512; o; o >>= 1) {
        if (tid < o) { sl[tid] += sl[tid + o]; sc[tid] += sc[tid + o]; }
        __syncthreads();
    }
    if (tid == 0) out[0] = (sc[0] > 0) ? (sl[0] / (float)sc[0]) : 0.0f;
}

// ---------------------------------------------------------------------------
extern "C" void kernel_launch(void* const* d_in, const int* in_sizes, int n_in,
                              void* d_out, int out_size) {
    const float* emb    = (const float*)d_in[0];
    const void*  labels = d_in[1];

    prep_kernel<<<1, 256>>>(labels);
    normalize_kernel<<<NB * 32 / 256, 256>>>(emb);

    sim_kernel<<<NTILES, 256>>>();

    reduce_kernel<<<1, 1024>>>((float*)d_out);
}